// round 17
// baseline (speedup 1.0000x reference)
#include <cuda_runtime.h>
#include <cstdint>

#define BATCH        8192
#define CHAN         4096
#define KWIN         5
#define THREADS      256
#define RB           8      // rows per load batch (24 independent LDGs in flight)
#define NBATCH       4      // batches per thread -> 32 rows
#define ROWS_PER_CTA (RB * NBATCH)

// out[b,i] = sum_k W[i,k] * x[b, i+k-2] (zero-padded) + bias[i]
// Pure register pipeline: thread = 4 channels x 32 rows, processed as 4
// batches of 8 rows. Each batch issues 8x(float4 + 2xfloat2) = 24 independent
// loads (256B/thread in flight) before any consumption. __launch_bounds__(256,2)
// grants 128 regs so ptxas can keep the whole batch register-resident.
// No smem, no barriers, no cp.async bookkeeping.
__global__ __launch_bounds__(THREADS, 2) void grouped_linear_kernel(
    const float* __restrict__ x,
    const float* __restrict__ W,
    const float* __restrict__ bias,
    float* __restrict__ out)
{
    const int c    = (blockIdx.x * THREADS + threadIdx.x) * 4;  // channel base
    const int row0 = blockIdx.y * ROWS_PER_CTA;

    // ---- per-thread constants: W[c..c+3][0..4] (20 floats, 16B-aligned) ----
    const float4* wv = reinterpret_cast<const float4*>(W + (size_t)c * KWIN);
    const float4 wa = wv[0];
    const float4 wb = wv[1];
    const float4 wc = wv[2];
    const float4 wd = wv[3];
    const float4 we = wv[4];
    const float4 bb = *reinterpret_cast<const float4*>(bias + c);

    const bool has_left  = (c > 0);            // x[c-2..c-1] valid
    const bool has_right = (c + 4 < CHAN);     // x[c+4..c+5] valid
    const float2 zero2 = make_float2(0.f, 0.f);

    const float* xr = x   + (size_t)row0 * CHAN + c;
    float*       op = out + (size_t)row0 * CHAN + c;

#pragma unroll
    for (int h = 0; h < NBATCH; h++) {
        float4 v [RB];
        float2 lo[RB];     // x[c-2], x[c-1]
        float2 hi[RB];     // x[c+4], x[c+5]

        // ---- load phase: 3*RB independent loads, all issued up front ----
#pragma unroll
        for (int r = 0; r < RB; r++) {
            const float* p = xr + (size_t)r * CHAN;
            v[r]  = *reinterpret_cast<const float4*>(p);
            lo[r] = has_left  ? *reinterpret_cast<const float2*>(p - 2) : zero2;
            hi[r] = has_right ? *reinterpret_cast<const float2*>(p + 4) : zero2;
        }

        // ---- compute + store phase ----
#pragma unroll
        for (int r = 0; r < RB; r++) {
            const float xm2 = lo[r].x, xm1 = lo[r].y;
            const float xp4 = hi[r].x, xp5 = hi[r].y;
            const float4 cv = v[r];

            float4 o;
            o.x = fmaf(wa.x, xm2,  fmaf(wa.y, xm1,  fmaf(wa.z, cv.x,
                  fmaf(wa.w, cv.y, fmaf(wb.x, cv.z, bb.x)))));
            o.y = fmaf(wb.y, xm1,  fmaf(wb.z, cv.x, fmaf(wb.w, cv.y,
                  fmaf(wc.x, cv.z, fmaf(wc.y, cv.w, bb.y)))));
            o.z = fmaf(wc.z, cv.x, fmaf(wc.w, cv.y, fmaf(wd.x, cv.z,
                  fmaf(wd.y, cv.w, fmaf(wd.z, xp4,  bb.z)))));
            o.w = fmaf(wd.w, cv.y, fmaf(we.x, cv.z, fmaf(we.y, cv.w,
                  fmaf(we.z, xp4,  fmaf(we.w, xp5,  bb.w)))));

            *reinterpret_cast<float4*>(op + (size_t)r * CHAN) = o;
        }

        xr += (size_t)RB * CHAN;
        op += (size_t)RB * CHAN;
    }
}

extern "C" void kernel_launch(void* const* d_in, const int* in_sizes, int n_in,
                              void* d_out, int out_size)
{
    const float* x    = (const float*)d_in[0];
    const float* W    = (const float*)d_in[1];
    const float* bias = (const float*)d_in[2];
    float* out        = (float*)d_out;

    dim3 block(THREADS);
    dim3 grid(CHAN / (4 * THREADS), BATCH / ROWS_PER_CTA);  // (4, 256) = 1024 CTAs
    grouped_linear_kernel<<<grid, block>>>(x, W, bias, out);
}